// round 11
// baseline (speedup 1.0000x reference)
#include <cuda_runtime.h>
#include <math.h>

#define N_NODES 512
#define TDIM 288
#define LDIM 128
#define BBATCH 4
#define MROWS (BBATCH * N_NODES)   // 2048

typedef unsigned long long u64;
typedef unsigned int u32;

// ---- packed f32x2 helpers (sm_100+) ----
__device__ __forceinline__ u64 add2(u64 a, u64 b) {
    u64 r; asm("add.rn.f32x2 %0,%1,%2;" : "=l"(r) : "l"(a), "l"(b)); return r;
}
__device__ __forceinline__ u64 fma2(u64 a, u64 b, u64 c) {
    u64 r; asm("fma.rn.f32x2 %0,%1,%2,%3;" : "=l"(r) : "l"(a), "l"(b), "l"(c)); return r;
}
__device__ __forceinline__ float lo32(u64 v) { return __uint_as_float((unsigned)(v & 0xffffffffu)); }
__device__ __forceinline__ float hi32(u64 v) { return __uint_as_float((unsigned)(v >> 32)); }
__device__ __forceinline__ u64 pack2(float x, float y) {
    return ((u64)__float_as_uint(y) << 32) | (u64)__float_as_uint(x);
}

// ---- tf32 helpers ----
__device__ __forceinline__ float to_tf32(float v) {
    u32 r; asm("cvt.rna.tf32.f32 %0,%1;" : "=r"(r) : "f"(v));
    return __uint_as_float(r);
}
__device__ __forceinline__ void mma_tf32(float* d, const u32* a, const u32* b) {
    asm("mma.sync.aligned.m16n8k8.row.col.f32.tf32.tf32.f32 "
        "{%0,%1,%2,%3}, {%4,%5,%6,%7}, {%8,%9}, {%0,%1,%2,%3};"
        : "+f"(d[0]), "+f"(d[1]), "+f"(d[2]), "+f"(d[3])
        : "r"(a[0]), "r"(a[1]), "r"(a[2]), "r"(a[3]), "r"(b[0]), "r"(b[1]));
}

// Scratch (device globals)
__device__ float g_X1[MROWS * LDIM];
__device__ float g_X2[MROWS * LDIM];
__device__ float g_S1[MROWS * LDIM];
__device__ float g_S2P[MROWS * LDIM];
__device__ float g_P[BBATCH * N_NODES * N_NODES];
__device__ float g_wh[256 * TDIM];          // [W1;W2] tf32-hi
__device__ float g_wl[256 * TDIM];          // [W1;W2] tf32-lo
__device__ float g_wph[2 * 128 * 128];      // Wp [z][n][k] hi
__device__ float g_wpl[2 * 128 * 128];      // lo
__device__ u32   g_cnt[128];                // pairwise tile counters (mod-4 parity)

// ---------------------------------------------------------------------------
// Prep: split weights into tf32 hi/lo planes (small; once per launch).
// ---------------------------------------------------------------------------
#define N_W  (256 * TDIM)          // 73728
#define N_WP (2 * 128 * 128)       // 32768

__global__ __launch_bounds__(256)
void prep_split(const float* __restrict__ W1, const float* __restrict__ W2,
                const float* __restrict__ Wp)
{
    int idx = blockIdx.x * 256 + threadIdx.x;
    if (idx >= N_W + N_WP) return;
    float v; float* H; float* L; int o;
    if (idx < N_W) {
        o = idx;
        int r = o / TDIM, k = o - r * TDIM;
        v = (r < 128) ? W1[r * TDIM + k] : W2[(r - 128) * TDIM + k];
        H = g_wh; L = g_wl;
    } else {
        o = idx - N_W;
        int z = o >> 14, rem = o & 16383;
        int n = rem >> 7, k = rem & 127;
        v = Wp[n * 256 + z * 128 + k];
        H = g_wph; L = g_wpl;
    }
    float h = to_tf32(v);
    H[o] = h;
    L[o] = to_tf32(v - h);
}

// ---------------------------------------------------------------------------
// 3xTF32 mma GEMM core. BM=32, BN=64, BK=32, 8 warps, double-buffered
// dynamic smem, 2-deep register prefetch. B side pre-split (pure copy).
// ---------------------------------------------------------------------------
#define SPAD 36
#define GA_SZ (32 * SPAD)
#define GB_SZ (64 * SPAD)
#define OFF_AH(buf) ((buf) * GA_SZ)
#define OFF_AL(buf) (2 * GA_SZ + (buf) * GA_SZ)
#define OFF_BH(buf) (4 * GA_SZ + (buf) * GB_SZ)
#define OFF_BL(buf) (4 * GA_SZ + 2 * GB_SZ + (buf) * GB_SZ)
#define GEMM_SMEM_FLOATS (4 * GA_SZ + 4 * GB_SZ)   // 13824 floats = 55296 B

__device__ __forceinline__ void split_store(float* H, float* L, int idx4, float4 v) {
    float4 h, l;
    h.x = to_tf32(v.x); l.x = to_tf32(v.x - h.x);
    h.y = to_tf32(v.y); l.y = to_tf32(v.y - h.y);
    h.z = to_tf32(v.z); l.z = to_tf32(v.z - h.z);
    h.w = to_tf32(v.w); l.w = to_tf32(v.w - h.w);
    *(float4*)(H + idx4) = h;
    *(float4*)(L + idx4) = l;
}

__device__ __forceinline__ void mma_chunk32(float acc[2][4],
                                            const float* Ah, const float* Al,
                                            const float* Bh, const float* Bl,
                                            int wm, int wn, int gid, int ctid) {
    const u32* AhU = (const u32*)Ah; const u32* AlU = (const u32*)Al;
    const u32* BhU = (const u32*)Bh; const u32* BlU = (const u32*)Bl;
    const int ar0 = (wm * 16 + gid) * SPAD;
    const int ar1 = (wm * 16 + gid + 8) * SPAD;
#pragma unroll
    for (int kk = 0; kk < 4; kk++) {
        int k8 = kk * 8;
        u32 ah[4], al[4], bh[2][2], bl[2][2];
        ah[0] = AhU[ar0 + k8 + ctid];     ah[1] = AhU[ar1 + k8 + ctid];
        ah[2] = AhU[ar0 + k8 + ctid + 4]; ah[3] = AhU[ar1 + k8 + ctid + 4];
        al[0] = AlU[ar0 + k8 + ctid];     al[1] = AlU[ar1 + k8 + ctid];
        al[2] = AlU[ar0 + k8 + ctid + 4]; al[3] = AlU[ar1 + k8 + ctid + 4];
#pragma unroll
        for (int nf = 0; nf < 2; nf++) {
            int r = (wn * 16 + nf * 8 + gid) * SPAD;
            bh[nf][0] = BhU[r + k8 + ctid];
            bh[nf][1] = BhU[r + k8 + ctid + 4];
            bl[nf][0] = BlU[r + k8 + ctid];
            bl[nf][1] = BlU[r + k8 + ctid + 4];
        }
#pragma unroll
        for (int nf = 0; nf < 2; nf++) {
            mma_tf32(acc[nf], ah, bh[nf]);
            mma_tf32(acc[nf], ah, bl[nf]);
            mma_tf32(acc[nf], al, bh[nf]);
        }
    }
}

// Stage 1: [X1|X2] = leaky(x @ [W1;W2]^T + bias). grid (64, 4).
__global__ __launch_bounds__(256)
void stage1_mma(const float* __restrict__ x,
                const float* __restrict__ b1, const float* __restrict__ b2,
                float* __restrict__ X1, float* __restrict__ X2)
{
    extern __shared__ __align__(16) float gsm[];

    const int t = threadIdx.x;
    const int lane = t & 31, warp = t >> 5;
    const int wm = warp >> 2, wn = warp & 3;
    const int gid = lane >> 2, ctid = lane & 3;
    const int m0 = blockIdx.x * 32;
    const int n0 = blockIdx.y * 64;

    const int arI = t >> 3, ak = (t & 7) * 4;
    const int brI = t >> 2, bk = (t & 3) * 8;

    const float* arow = x + (size_t)(m0 + arI) * TDIM + ak;
    const float* bhrow = g_wh + (size_t)(n0 + brI) * TDIM + bk;
    const float* blrow = g_wl + (size_t)(n0 + brI) * TDIM + bk;

    float acc[2][4] = {};
    const int nt = TDIM / 32;        // 9

    float4 rA, rBh0, rBh1, rBl0, rBl1;
    rA   = *(const float4*)(arow);
    rBh0 = *(const float4*)(bhrow);      rBh1 = *(const float4*)(bhrow + 4);
    rBl0 = *(const float4*)(blrow);      rBl1 = *(const float4*)(blrow + 4);
    split_store(gsm + OFF_AH(0), gsm + OFF_AL(0), arI * SPAD + ak, rA);
    *(float4*)(gsm + OFF_BH(0) + brI * SPAD + bk)     = rBh0;
    *(float4*)(gsm + OFF_BH(0) + brI * SPAD + bk + 4) = rBh1;
    *(float4*)(gsm + OFF_BL(0) + brI * SPAD + bk)     = rBl0;
    *(float4*)(gsm + OFF_BL(0) + brI * SPAD + bk + 4) = rBl1;
    rA   = *(const float4*)(arow + 32);
    rBh0 = *(const float4*)(bhrow + 32); rBh1 = *(const float4*)(bhrow + 36);
    rBl0 = *(const float4*)(blrow + 32); rBl1 = *(const float4*)(blrow + 36);
    __syncthreads();

    for (int ti = 0; ti < nt; ti++) {
        int cur = ti & 1;
        if (ti + 1 < nt) {
            int nx = cur ^ 1;
            split_store(gsm + OFF_AH(nx), gsm + OFF_AL(nx), arI * SPAD + ak, rA);
            *(float4*)(gsm + OFF_BH(nx) + brI * SPAD + bk)     = rBh0;
            *(float4*)(gsm + OFF_BH(nx) + brI * SPAD + bk + 4) = rBh1;
            *(float4*)(gsm + OFF_BL(nx) + brI * SPAD + bk)     = rBl0;
            *(float4*)(gsm + OFF_BL(nx) + brI * SPAD + bk + 4) = rBl1;
            if (ti + 2 < nt) {
                int k0 = (ti + 2) * 32;
                rA   = *(const float4*)(arow + k0);
                rBh0 = *(const float4*)(bhrow + k0); rBh1 = *(const float4*)(bhrow + k0 + 4);
                rBl0 = *(const float4*)(blrow + k0); rBl1 = *(const float4*)(blrow + k0 + 4);
            }
        }
        mma_chunk32(acc, gsm + OFF_AH(cur), gsm + OFF_AL(cur),
                    gsm + OFF_BH(cur), gsm + OFF_BL(cur), wm, wn, gid, ctid);
        __syncthreads();
    }

    const int half = (n0 < 128);
    float* OUT = half ? X1 : X2;
    const float* bias = half ? b1 : b2;
    const int nloc0 = half ? n0 : n0 - 128;
    const int row = m0 + wm * 16 + gid;
#pragma unroll
    for (int nf = 0; nf < 2; nf++) {
        int col = nloc0 + wn * 16 + nf * 8 + 2 * ctid;
        float v0 = acc[nf][0] + bias[col];
        float v1 = acc[nf][1] + bias[col + 1];
        float v2 = acc[nf][2] + bias[col];
        float v3 = acc[nf][3] + bias[col + 1];
        v0 = fmaxf(v0, 0.2f * v0); v1 = fmaxf(v1, 0.2f * v1);
        v2 = fmaxf(v2, 0.2f * v2); v3 = fmaxf(v3, 0.2f * v3);
        *(float2*)&OUT[(size_t)row * LDIM + col]       = make_float2(v0, v1);
        *(float2*)&OUT[(size_t)(row + 8) * LDIM + col] = make_float2(v2, v3);
    }
}

// Stage 2: z=0: S1 = X1 @ Wp_a^T ; z=1: S2P = X2 @ Wp_b^T + bp. grid (64,2,2).
__global__ __launch_bounds__(256)
void stage2_mma(const float* __restrict__ X1, const float* __restrict__ X2,
                const float* __restrict__ bp,
                float* __restrict__ S1, float* __restrict__ S2P)
{
    extern __shared__ __align__(16) float gsm[];

    const int t = threadIdx.x;
    const int lane = t & 31, warp = t >> 5;
    const int wm = warp >> 2, wn = warp & 3;
    const int gid = lane >> 2, ctid = lane & 3;
    const int m0 = blockIdx.x * 32;
    const int n0 = blockIdx.y * 64;
    const int z  = blockIdx.z;

    const float* A = z ? X2 : X1;
    const int arI = t >> 3, ak = (t & 7) * 4;
    const int brI = t >> 2, bk = (t & 3) * 8;
    const float* arow  = A + (size_t)(m0 + arI) * LDIM + ak;
    const float* bhrow = g_wph + (size_t)z * 16384 + (size_t)(n0 + brI) * 128 + bk;
    const float* blrow = g_wpl + (size_t)z * 16384 + (size_t)(n0 + brI) * 128 + bk;

    float acc[2][4] = {};
    const int nt = LDIM / 32;        // 4

    float4 rA, rBh0, rBh1, rBl0, rBl1;
    rA   = *(const float4*)(arow);
    rBh0 = *(const float4*)(bhrow);      rBh1 = *(const float4*)(bhrow + 4);
    rBl0 = *(const float4*)(blrow);      rBl1 = *(const float4*)(blrow + 4);
    split_store(gsm + OFF_AH(0), gsm + OFF_AL(0), arI * SPAD + ak, rA);
    *(float4*)(gsm + OFF_BH(0) + brI * SPAD + bk)     = rBh0;
    *(float4*)(gsm + OFF_BH(0) + brI * SPAD + bk + 4) = rBh1;
    *(float4*)(gsm + OFF_BL(0) + brI * SPAD + bk)     = rBl0;
    *(float4*)(gsm + OFF_BL(0) + brI * SPAD + bk + 4) = rBl1;
    rA   = *(const float4*)(arow + 32);
    rBh0 = *(const float4*)(bhrow + 32); rBh1 = *(const float4*)(bhrow + 36);
    rBl0 = *(const float4*)(blrow + 32); rBl1 = *(const float4*)(blrow + 36);
    __syncthreads();

    for (int ti = 0; ti < nt; ti++) {
        int cur = ti & 1;
        if (ti + 1 < nt) {
            int nx = cur ^ 1;
            split_store(gsm + OFF_AH(nx), gsm + OFF_AL(nx), arI * SPAD + ak, rA);
            *(float4*)(gsm + OFF_BH(nx) + brI * SPAD + bk)     = rBh0;
            *(float4*)(gsm + OFF_BH(nx) + brI * SPAD + bk + 4) = rBh1;
            *(float4*)(gsm + OFF_BL(nx) + brI * SPAD + bk)     = rBl0;
            *(float4*)(gsm + OFF_BL(nx) + brI * SPAD + bk + 4) = rBl1;
            if (ti + 2 < nt) {
                int k0 = (ti + 2) * 32;
                rA   = *(const float4*)(arow + k0);
                rBh0 = *(const float4*)(bhrow + k0); rBh1 = *(const float4*)(bhrow + k0 + 4);
                rBl0 = *(const float4*)(blrow + k0); rBl1 = *(const float4*)(blrow + k0 + 4);
            }
        }
        mma_chunk32(acc, gsm + OFF_AH(cur), gsm + OFF_AL(cur),
                    gsm + OFF_BH(cur), gsm + OFF_BL(cur), wm, wn, gid, ctid);
        __syncthreads();
    }

    float* OUT = z ? S2P : S1;
    const int row = m0 + wm * 16 + gid;
#pragma unroll
    for (int nf = 0; nf < 2; nf++) {
        int col = n0 + wn * 16 + nf * 8 + 2 * ctid;
        float bv0 = z ? bp[col] : 0.f;
        float bv1 = z ? bp[col + 1] : 0.f;
        *(float2*)&OUT[(size_t)row * LDIM + col]       = make_float2(acc[nf][0] + bv0, acc[nf][1] + bv1);
        *(float2*)&OUT[(size_t)(row + 8) * LDIM + col] = make_float2(acc[nf][2] + bv0, acc[nf][3] + bv1);
    }
}

// ---------------------------------------------------------------------------
// Pairwise + fused finalize tail. grid (16 jx, 8 iy, 4 b), 128 threads.
// The 4th block finishing an (i0,j0) tile (atomic counter, mod-4 parity so
// no reset needed across graph replays) runs the mean/mask/logit/noise
// epilogue for that tile and writes out directly.
// ---------------------------------------------------------------------------
#define SR2 65   // u64 per row (64 + 1 pad)
#define PW_S2   4160
#define PW_C1   6240
#define PW_C2   6304
#define PW_ROWF 12736           // float index of rowA
#define PW_U64_TOTAL 6416       // 51,328 bytes

__global__ __launch_bounds__(128)
void pairwise_final_kernel(const float* __restrict__ S1, const float* __restrict__ S2P,
                           const float* __restrict__ Wb, const float* __restrict__ bb,
                           const float* __restrict__ noise,
                           float* __restrict__ P, float* __restrict__ out)
{
    extern __shared__ __align__(16) u64 sm[];
    __shared__ u32 sh_last;
    u64*   s1t  = sm;
    u64*   s2t  = sm + PW_S2;
    u64*   c1   = sm + PW_C1;
    u64*   c2   = sm + PW_C2;
    float* rowA = ((float*)sm) + PW_ROWF;        // [64]
    float* rowB = rowA + 64;                     // [32]

    const int t  = threadIdx.x;
    const int tx = t & 7;           // j micro col 0..7
    const int ty = t >> 3;          // i micro row 0..15
    const int j0 = blockIdx.x * 32;
    const int i0 = blockIdx.y * 64;
    const int b  = blockIdx.z;

    if (t < 64) {
        float2 w = ((const float2*)Wb)[t];
        c1[t] = pack2(0.6f * w.x, 0.6f * w.y);
        c2[t] = pack2(0.4f * w.x, 0.4f * w.y);
    }

    const float4* S1v = (const float4*)(S1  + ((size_t)b * N_NODES + i0) * LDIM);
    const float4* S2v = (const float4*)(S2P + ((size_t)b * N_NODES + j0) * LDIM);
#pragma unroll
    for (int s = 0; s < 16; s++) {
        int f   = t + s * 128;
        int row = f >> 5;
        int c4  = f & 31;
        float4 v = S1v[row * 32 + c4];
        float2* d = (float2*)&s1t[row * SR2 + c4 * 2];
        d[0] = make_float2(v.x, v.y);
        d[1] = make_float2(v.z, v.w);
    }
#pragma unroll
    for (int s = 0; s < 8; s++) {
        int f   = t + s * 128;
        int row = f >> 5;
        int c4  = f & 31;
        float4 v = S2v[row * 32 + c4];
        float2* d = (float2*)&s2t[row * SR2 + c4 * 2];
        d[0] = make_float2(v.x, v.y);
        d[1] = make_float2(v.z, v.w);
    }
    __syncthreads();

    // separable linear parts
    {
        int row  = t >> 1;
        int half = t & 1;
        const u64* src = s1t + row * SR2 + half * 32;
        const u64* cc  = c1 + half * 32;
        u64 a0 = 0, a1 = 0;
#pragma unroll
        for (int q = 0; q < 32; q += 2) {
            a0 = fma2(cc[q],     src[q],     a0);
            a1 = fma2(cc[q + 1], src[q + 1], a1);
        }
        float s = lo32(a0) + hi32(a0) + lo32(a1) + hi32(a1);
        s += __shfl_xor_sync(0xffffffffu, s, 1);
        if (half == 0) rowA[row] = s;
    }
    if (t < 64) {
        int row  = t >> 1;
        int half = t & 1;
        const u64* src = s2t + row * SR2 + half * 32;
        const u64* cc  = c1 + half * 32;
        u64 a0 = 0, a1 = 0;
#pragma unroll
        for (int q = 0; q < 32; q += 2) {
            a0 = fma2(cc[q],     src[q],     a0);
            a1 = fma2(cc[q + 1], src[q + 1], a1);
        }
        float s = lo32(a0) + hi32(a0) + lo32(a1) + hi32(a1);
        s += __shfl_xor_sync(0xffffffffu, s, 1);
        if (half == 0) rowB[row] = s;
    }
    __syncthreads();

    u64 acc[4][4] = {};
    const u64 MASK = 0x7fffffff7fffffffULL;
#pragma unroll 2
    for (int kk = 0; kk < 64; kk++) {
        u64 cw = c2[kk];
        u64 ra[4], rb[4];
#pragma unroll
        for (int r = 0; r < 4; r++) ra[r] = s1t[(ty + 16 * r) * SR2 + kk];
#pragma unroll
        for (int c = 0; c < 4; c++) rb[c] = s2t[(tx + 8 * c) * SR2 + kk];
#pragma unroll
        for (int r = 0; r < 4; r++)
#pragma unroll
            for (int c = 0; c < 4; c++) {
                u64 v = add2(ra[r], rb[c]);
                acc[r][c] = fma2(cw, v & MASK, acc[r][c]);
            }
    }

    const float bbv = bb[0];
    float* Pb = P + (size_t)b * N_NODES * N_NODES;
#pragma unroll
    for (int r = 0; r < 4; r++) {
        int i = i0 + ty + 16 * r;
        float ai = rowA[ty + 16 * r];
#pragma unroll
        for (int c = 0; c < 4; c++) {
            int j = j0 + tx + 8 * c;
            float z = lo32(acc[r][c]) + hi32(acc[r][c])
                    + ai + rowB[tx + 8 * c] + bbv;
            Pb[(size_t)i * N_NODES + j] = 1.f / (1.f + __expf(-z));
        }
    }

    // ---- fused finalize tail (threadFenceReduction pattern) ----
    __threadfence();
    __syncthreads();
    if (t == 0) {
        u32 old = atomicAdd(&g_cnt[blockIdx.y * 16 + blockIdx.x], 1u);
        sh_last = ((old & 3u) == 3u) ? 1u : 0u;
    }
    __syncthreads();
    if (!sh_last) return;
    __threadfence();

    const int PL = N_NODES * N_NODES;
#pragma unroll
    for (int e = 0; e < 16; e++) {
        int o = e * 128 + t;            // 0..2047
        int gi = i0 + (o >> 5);
        int gj = j0 + (o & 31);
        size_t idx = (size_t)gi * N_NODES + gj;
        float p = 0.25f * (P[idx] + P[idx + PL] + P[idx + 2 * PL] + P[idx + 3 * PL]);
        if (gi == gj) p = 0.f;
        float lp = __logf(p + 1e-10f) - __logf(1.0f + (1e-10f - p));
        lp = fminf(fmaxf(lp, -10.f), 10.f);
        float ns = noise[idx];
        float lo = __logf(ns) - __logf(1.0f - ns);
        float z = (lp + lo) * 5.0f;     // / TEMPERATURE (0.2)
        out[idx] = 1.f / (1.f + __expf(-z));
    }
}

// ---------------------------------------------------------------------------
extern "C" void kernel_launch(void* const* d_in, const int* in_sizes, int n_in,
                              void* d_out, int out_size)
{
    const float* x     = (const float*)d_in[0];
    const float* W1    = (const float*)d_in[1];
    const float* b1    = (const float*)d_in[2];
    const float* W2    = (const float*)d_in[3];
    const float* b2    = (const float*)d_in[4];
    const float* Wp    = (const float*)d_in[5];
    const float* bp    = (const float*)d_in[6];
    const float* Wb    = (const float*)d_in[7];
    const float* bb    = (const float*)d_in[8];
    const float* noise = (const float*)d_in[9];
    float* out = (float*)d_out;

    float *X1, *X2, *S1, *S2P, *P;
    cudaGetSymbolAddress((void**)&X1,  g_X1);
    cudaGetSymbolAddress((void**)&X2,  g_X2);
    cudaGetSymbolAddress((void**)&S1,  g_S1);
    cudaGetSymbolAddress((void**)&S2P, g_S2P);
    cudaGetSymbolAddress((void**)&P,   g_P);

    const size_t gemm_smem = (size_t)GEMM_SMEM_FLOATS * sizeof(float);  // 55296 B
    cudaFuncSetAttribute(stage1_mma, cudaFuncAttributeMaxDynamicSharedMemorySize,
                         (int)gemm_smem);
    cudaFuncSetAttribute(stage2_mma, cudaFuncAttributeMaxDynamicSharedMemorySize,
                         (int)gemm_smem);

    // Stage 0: split weights into tf32 hi/lo planes (small)
    prep_split<<<(N_W + N_WP + 255) / 256, 256>>>(W1, W2, Wp);

    // Stage 1: [X1|X2] = leaky(x @ [W1;W2]^T + bias)
    stage1_mma<<<dim3(MROWS / 32, 4), 256, gemm_smem>>>(x, b1, b2, X1, X2);

    // Stage 2: S1 = X1@Wp_a^T, S2P = X2@Wp_b^T + bp
    stage2_mma<<<dim3(MROWS / 32, 2, 2), 256, gemm_smem>>>(X1, X2, bp, S1, S2P);

    // Stage 3: pairwise sigmoid planes + fused finalize tail
    size_t pw_smem = (size_t)PW_U64_TOTAL * sizeof(u64);   // 51,328 B
    cudaFuncSetAttribute(pairwise_final_kernel,
                         cudaFuncAttributeMaxDynamicSharedMemorySize, (int)pw_smem);
    dim3 g3(N_NODES / 32, N_NODES / 64, BBATCH);   // 16 x 8 x 4 = 512
    pairwise_final_kernel<<<g3, dim3(128), pw_smem>>>(S1, S2P, Wb, bb, noise, P, out);
}

// round 12
// speedup vs baseline: 1.2187x; 1.2187x over previous
#include <cuda_runtime.h>
#include <math.h>

#define N_NODES 512
#define TDIM 288
#define LDIM 128
#define BBATCH 4
#define MROWS (BBATCH * N_NODES)   // 2048

typedef unsigned long long u64;
typedef unsigned int u32;

// ---- packed f32x2 helpers (sm_100+) ----
__device__ __forceinline__ u64 add2(u64 a, u64 b) {
    u64 r; asm("add.rn.f32x2 %0,%1,%2;" : "=l"(r) : "l"(a), "l"(b)); return r;
}
__device__ __forceinline__ u64 fma2(u64 a, u64 b, u64 c) {
    u64 r; asm("fma.rn.f32x2 %0,%1,%2,%3;" : "=l"(r) : "l"(a), "l"(b), "l"(c)); return r;
}
__device__ __forceinline__ float lo32(u64 v) { return __uint_as_float((unsigned)(v & 0xffffffffu)); }
__device__ __forceinline__ float hi32(u64 v) { return __uint_as_float((unsigned)(v >> 32)); }
__device__ __forceinline__ u64 pack2(float x, float y) {
    return ((u64)__float_as_uint(y) << 32) | (u64)__float_as_uint(x);
}

// ---- tf32 helpers ----
__device__ __forceinline__ float to_tf32(float v) {
    u32 r; asm("cvt.rna.tf32.f32 %0,%1;" : "=r"(r) : "f"(v));
    return __uint_as_float(r);
}
__device__ __forceinline__ void mma_tf32(float* d, const u32* a, const u32* b) {
    asm("mma.sync.aligned.m16n8k8.row.col.f32.tf32.tf32.f32 "
        "{%0,%1,%2,%3}, {%4,%5,%6,%7}, {%8,%9}, {%0,%1,%2,%3};"
        : "+f"(d[0]), "+f"(d[1]), "+f"(d[2]), "+f"(d[3])
        : "r"(a[0]), "r"(a[1]), "r"(a[2]), "r"(a[3]), "r"(b[0]), "r"(b[1]));
}

// Scratch (device globals)
__device__ float g_X1[MROWS * LDIM];
__device__ float g_X2[MROWS * LDIM];
__device__ float g_S1[MROWS * LDIM];
__device__ float g_S2P[MROWS * LDIM];
__device__ float g_P[BBATCH * N_NODES * N_NODES];

// ---------------------------------------------------------------------------
// 3xTF32 mma GEMM core (R8 design — proven). BM=32, BN=64, BK=32, 8 warps,
// double-buffered dynamic smem, 2-deep register prefetch.
// ---------------------------------------------------------------------------
#define SPAD 36
#define GA_SZ (32 * SPAD)
#define GB_SZ (64 * SPAD)
#define OFF_AH(buf) ((buf) * GA_SZ)
#define OFF_AL(buf) (2 * GA_SZ + (buf) * GA_SZ)
#define OFF_BH(buf) (4 * GA_SZ + (buf) * GB_SZ)
#define OFF_BL(buf) (4 * GA_SZ + 2 * GB_SZ + (buf) * GB_SZ)
#define GEMM_SMEM_FLOATS (4 * GA_SZ + 4 * GB_SZ)   // 13824 floats = 55296 B

__device__ __forceinline__ void split_store(float* H, float* L, int idx4, float4 v) {
    float4 h, l;
    h.x = to_tf32(v.x); l.x = to_tf32(v.x - h.x);
    h.y = to_tf32(v.y); l.y = to_tf32(v.y - h.y);
    h.z = to_tf32(v.z); l.z = to_tf32(v.z - h.z);
    h.w = to_tf32(v.w); l.w = to_tf32(v.w - h.w);
    *(float4*)(H + idx4) = h;
    *(float4*)(L + idx4) = l;
}

__device__ __forceinline__ void mma_chunk32(float acc[2][4],
                                            const float* Ah, const float* Al,
                                            const float* Bh, const float* Bl,
                                            int wm, int wn, int gid, int ctid) {
    const u32* AhU = (const u32*)Ah; const u32* AlU = (const u32*)Al;
    const u32* BhU = (const u32*)Bh; const u32* BlU = (const u32*)Bl;
    const int ar0 = (wm * 16 + gid) * SPAD;
    const int ar1 = (wm * 16 + gid + 8) * SPAD;
#pragma unroll
    for (int kk = 0; kk < 4; kk++) {
        int k8 = kk * 8;
        u32 ah[4], al[4], bh[2][2], bl[2][2];
        ah[0] = AhU[ar0 + k8 + ctid];     ah[1] = AhU[ar1 + k8 + ctid];
        ah[2] = AhU[ar0 + k8 + ctid + 4]; ah[3] = AhU[ar1 + k8 + ctid + 4];
        al[0] = AlU[ar0 + k8 + ctid];     al[1] = AlU[ar1 + k8 + ctid];
        al[2] = AlU[ar0 + k8 + ctid + 4]; al[3] = AlU[ar1 + k8 + ctid + 4];
#pragma unroll
        for (int nf = 0; nf < 2; nf++) {
            int r = (wn * 16 + nf * 8 + gid) * SPAD;
            bh[nf][0] = BhU[r + k8 + ctid];
            bh[nf][1] = BhU[r + k8 + ctid + 4];
            bl[nf][0] = BlU[r + k8 + ctid];
            bl[nf][1] = BlU[r + k8 + ctid + 4];
        }
#pragma unroll
        for (int nf = 0; nf < 2; nf++) {
            mma_tf32(acc[nf], ah, bh[nf]);
            mma_tf32(acc[nf], ah, bl[nf]);
            mma_tf32(acc[nf], al, bh[nf]);
        }
    }
}

// Stage 1: [X1|X2] = leaky(x @ [W1;W2]^T + bias). grid (64, 4).
__global__ __launch_bounds__(256)
void stage1_mma(const float* __restrict__ x,
                const float* __restrict__ W1, const float* __restrict__ W2,
                const float* __restrict__ b1, const float* __restrict__ b2,
                float* __restrict__ X1, float* __restrict__ X2)
{
    extern __shared__ __align__(16) float gsm[];

    const int t = threadIdx.x;
    const int lane = t & 31, warp = t >> 5;
    const int wm = warp >> 2, wn = warp & 3;
    const int gid = lane >> 2, ctid = lane & 3;
    const int m0 = blockIdx.x * 32;
    const int n0 = blockIdx.y * 64;

    const int arI = t >> 3, ak = (t & 7) * 4;
    const int brI = t >> 2, bk = (t & 3) * 8;

    const float* arow = x + (size_t)(m0 + arI) * TDIM + ak;
    const float* wrow = (n0 + brI) < 128
        ? W1 + (size_t)(n0 + brI) * TDIM + bk
        : W2 + (size_t)(n0 + brI - 128) * TDIM + bk;

    float acc[2][4] = {};
    const int nt = TDIM / 32;        // 9

    float4 rA, rB0, rB1;
    rA  = *(const float4*)(arow);
    rB0 = *(const float4*)(wrow);
    rB1 = *(const float4*)(wrow + 4);
    split_store(gsm + OFF_AH(0), gsm + OFF_AL(0), arI * SPAD + ak, rA);
    split_store(gsm + OFF_BH(0), gsm + OFF_BL(0), brI * SPAD + bk, rB0);
    split_store(gsm + OFF_BH(0), gsm + OFF_BL(0), brI * SPAD + bk + 4, rB1);
    rA  = *(const float4*)(arow + 32);
    rB0 = *(const float4*)(wrow + 32);
    rB1 = *(const float4*)(wrow + 36);
    __syncthreads();

    for (int ti = 0; ti < nt; ti++) {
        int cur = ti & 1;
        if (ti + 1 < nt) {
            int nx = cur ^ 1;
            split_store(gsm + OFF_AH(nx), gsm + OFF_AL(nx), arI * SPAD + ak, rA);
            split_store(gsm + OFF_BH(nx), gsm + OFF_BL(nx), brI * SPAD + bk, rB0);
            split_store(gsm + OFF_BH(nx), gsm + OFF_BL(nx), brI * SPAD + bk + 4, rB1);
            if (ti + 2 < nt) {
                int k0 = (ti + 2) * 32;
                rA  = *(const float4*)(arow + k0);
                rB0 = *(const float4*)(wrow + k0);
                rB1 = *(const float4*)(wrow + k0 + 4);
            }
        }
        mma_chunk32(acc, gsm + OFF_AH(cur), gsm + OFF_AL(cur),
                    gsm + OFF_BH(cur), gsm + OFF_BL(cur), wm, wn, gid, ctid);
        __syncthreads();
    }

    const int half = (n0 < 128);
    float* OUT = half ? X1 : X2;
    const float* bias = half ? b1 : b2;
    const int nloc0 = half ? n0 : n0 - 128;
    const int row = m0 + wm * 16 + gid;
#pragma unroll
    for (int nf = 0; nf < 2; nf++) {
        int col = nloc0 + wn * 16 + nf * 8 + 2 * ctid;
        float v0 = acc[nf][0] + bias[col];
        float v1 = acc[nf][1] + bias[col + 1];
        float v2 = acc[nf][2] + bias[col];
        float v3 = acc[nf][3] + bias[col + 1];
        v0 = fmaxf(v0, 0.2f * v0); v1 = fmaxf(v1, 0.2f * v1);
        v2 = fmaxf(v2, 0.2f * v2); v3 = fmaxf(v3, 0.2f * v3);
        *(float2*)&OUT[(size_t)row * LDIM + col]       = make_float2(v0, v1);
        *(float2*)&OUT[(size_t)(row + 8) * LDIM + col] = make_float2(v2, v3);
    }
}

// Stage 2: z=0: S1 = X1 @ Wp_a^T ; z=1: S2P = X2 @ Wp_b^T + bp. grid (64,2,2).
__global__ __launch_bounds__(256)
void stage2_mma(const float* __restrict__ X1, const float* __restrict__ X2,
                const float* __restrict__ Wp, const float* __restrict__ bp,
                float* __restrict__ S1, float* __restrict__ S2P)
{
    extern __shared__ __align__(16) float gsm[];

    const int t = threadIdx.x;
    const int lane = t & 31, warp = t >> 5;
    const int wm = warp >> 2, wn = warp & 3;
    const int gid = lane >> 2, ctid = lane & 3;
    const int m0 = blockIdx.x * 32;
    const int n0 = blockIdx.y * 64;
    const int z  = blockIdx.z;

    const float* A = z ? X2 : X1;
    const int arI = t >> 3, ak = (t & 7) * 4;
    const int brI = t >> 2, bk = (t & 3) * 8;
    const float* arow = A + (size_t)(m0 + arI) * LDIM + ak;
    const float* wrow = Wp + (size_t)(n0 + brI) * (2 * LDIM) + z * LDIM + bk;

    float acc[2][4] = {};
    const int nt = LDIM / 32;        // 4

    float4 rA, rB0, rB1;
    rA  = *(const float4*)(arow);
    rB0 = *(const float4*)(wrow);
    rB1 = *(const float4*)(wrow + 4);
    split_store(gsm + OFF_AH(0), gsm + OFF_AL(0), arI * SPAD + ak, rA);
    split_store(gsm + OFF_BH(0), gsm + OFF_BL(0), brI * SPAD + bk, rB0);
    split_store(gsm + OFF_BH(0), gsm + OFF_BL(0), brI * SPAD + bk + 4, rB1);
    rA  = *(const float4*)(arow + 32);
    rB0 = *(const float4*)(wrow + 32);
    rB1 = *(const float4*)(wrow + 36);
    __syncthreads();

    for (int ti = 0; ti < nt; ti++) {
        int cur = ti & 1;
        if (ti + 1 < nt) {
            int nx = cur ^ 1;
            split_store(gsm + OFF_AH(nx), gsm + OFF_AL(nx), arI * SPAD + ak, rA);
            split_store(gsm + OFF_BH(nx), gsm + OFF_BL(nx), brI * SPAD + bk, rB0);
            split_store(gsm + OFF_BH(nx), gsm + OFF_BL(nx), brI * SPAD + bk + 4, rB1);
            if (ti + 2 < nt) {
                int k0 = (ti + 2) * 32;
                rA  = *(const float4*)(arow + k0);
                rB0 = *(const float4*)(wrow + k0);
                rB1 = *(const float4*)(wrow + k0 + 4);
            }
        }
        mma_chunk32(acc, gsm + OFF_AH(cur), gsm + OFF_AL(cur),
                    gsm + OFF_BH(cur), gsm + OFF_BL(cur), wm, wn, gid, ctid);
        __syncthreads();
    }

    float* OUT = z ? S2P : S1;
    const int row = m0 + wm * 16 + gid;
#pragma unroll
    for (int nf = 0; nf < 2; nf++) {
        int col = n0 + wn * 16 + nf * 8 + 2 * ctid;
        float bv0 = z ? bp[col] : 0.f;
        float bv1 = z ? bp[col + 1] : 0.f;
        *(float2*)&OUT[(size_t)row * LDIM + col]       = make_float2(acc[nf][0] + bv0, acc[nf][1] + bv1);
        *(float2*)&OUT[(size_t)(row + 8) * LDIM + col] = make_float2(acc[nf][2] + bv0, acc[nf][3] + bv1);
    }
}

// ---------------------------------------------------------------------------
// Pairwise: 64x64 tile per block (one b), grid (8, 8, 4), 128 threads.
// 4x8 u64 micro-tile per thread: 12 LDS.64 per 32 u64-MACs (0.375 loads/MAC)
// -> 25% less smem crossbar traffic than the 64x32/4x4 version.
// ---------------------------------------------------------------------------
#define SR2 65   // u64 per row (64 + 1 pad)
#define PW_S2   (64 * SR2)          // 4160
#define PW_C1   (2 * 64 * SR2)      // 8320
#define PW_C2   (PW_C1 + 64)        // 8384
#define PW_ROWF ((PW_C2 + 64) * 2)  // float index of rowA = 16896
#define PW_U64_TOTAL (PW_C2 + 64 + 64)  // 8512 u64 = 68,096 bytes

__global__ __launch_bounds__(128)
void pairwise_kernel(const float* __restrict__ S1, const float* __restrict__ S2P,
                     const float* __restrict__ Wb, const float* __restrict__ bb,
                     float* __restrict__ P)
{
    extern __shared__ __align__(16) u64 sm[];
    u64*   s1t  = sm;
    u64*   s2t  = sm + PW_S2;
    u64*   c1   = sm + PW_C1;
    u64*   c2   = sm + PW_C2;
    float* rowA = ((float*)sm) + PW_ROWF;        // [64]
    float* rowB = rowA + 64;                     // [64]

    const int t  = threadIdx.x;
    const int tx = t & 7;           // j micro col 0..7
    const int ty = t >> 3;          // i micro row 0..15
    const int j0 = blockIdx.x * 64;
    const int i0 = blockIdx.y * 64;
    const int b  = blockIdx.z;

    if (t < 64) {
        float2 w = ((const float2*)Wb)[t];
        c1[t] = pack2(0.6f * w.x, 0.6f * w.y);
        c2[t] = pack2(0.4f * w.x, 0.4f * w.y);
    }

    const float4* S1v = (const float4*)(S1  + ((size_t)b * N_NODES + i0) * LDIM);
    const float4* S2v = (const float4*)(S2P + ((size_t)b * N_NODES + j0) * LDIM);
#pragma unroll
    for (int s = 0; s < 16; s++) {
        int f   = t + s * 128;          // 0..2047
        int row = f >> 5;
        int c4  = f & 31;
        float4 v = S1v[row * 32 + c4];
        float4 w = S2v[row * 32 + c4];
        float2* d = (float2*)&s1t[row * SR2 + c4 * 2];
        d[0] = make_float2(v.x, v.y);
        d[1] = make_float2(v.z, v.w);
        float2* e = (float2*)&s2t[row * SR2 + c4 * 2];
        e[0] = make_float2(w.x, w.y);
        e[1] = make_float2(w.z, w.w);
    }
    __syncthreads();

    // separable linear parts: 2 threads per row, both arrays
    {
        int row  = t >> 1;
        int half = t & 1;
        const u64* cc = c1 + half * 32;
        const u64* srcA = s1t + row * SR2 + half * 32;
        const u64* srcB = s2t + row * SR2 + half * 32;
        u64 a0 = 0, a1 = 0, b0 = 0, b1 = 0;
#pragma unroll
        for (int q = 0; q < 32; q += 2) {
            a0 = fma2(cc[q],     srcA[q],     a0);
            a1 = fma2(cc[q + 1], srcA[q + 1], a1);
            b0 = fma2(cc[q],     srcB[q],     b0);
            b1 = fma2(cc[q + 1], srcB[q + 1], b1);
        }
        float sa = lo32(a0) + hi32(a0) + lo32(a1) + hi32(a1);
        float sb = lo32(b0) + hi32(b0) + lo32(b1) + hi32(b1);
        sa += __shfl_xor_sync(0xffffffffu, sa, 1);
        sb += __shfl_xor_sync(0xffffffffu, sb, 1);
        if (half == 0) { rowA[row] = sa; rowB[row] = sb; }
    }
    __syncthreads();

    u64 acc[4][8] = {};
    const u64 MASK = 0x7fffffff7fffffffULL;
#pragma unroll 2
    for (int kk = 0; kk < 64; kk++) {
        u64 cw = c2[kk];
        u64 ra[4], rb[8];
#pragma unroll
        for (int r = 0; r < 4; r++) ra[r] = s1t[(ty + 16 * r) * SR2 + kk];
#pragma unroll
        for (int c = 0; c < 8; c++) rb[c] = s2t[(tx + 8 * c) * SR2 + kk];
#pragma unroll
        for (int r = 0; r < 4; r++)
#pragma unroll
            for (int c = 0; c < 8; c++) {
                u64 v = add2(ra[r], rb[c]);
                acc[r][c] = fma2(cw, v & MASK, acc[r][c]);
            }
    }

    const float bbv = bb[0];
    float* Pb = P + (size_t)b * N_NODES * N_NODES;
#pragma unroll
    for (int r = 0; r < 4; r++) {
        int i = i0 + ty + 16 * r;
        float ai = rowA[ty + 16 * r] + bbv;
#pragma unroll
        for (int c = 0; c < 8; c++) {
            int j = j0 + tx + 8 * c;
            float z = lo32(acc[r][c]) + hi32(acc[r][c])
                    + ai + rowB[tx + 8 * c];
            Pb[(size_t)i * N_NODES + j] = 1.f / (1.f + __expf(-z));
        }
    }
}

// ---------------------------------------------------------------------------
// Finalize: p = mean_b P -> diag mask -> clamped logit -> +logistic(noise)
//           -> sigmoid(/0.2). One float4 per thread.
// ---------------------------------------------------------------------------
__global__ __launch_bounds__(128)
void finalize_kernel(const float* __restrict__ P, const float* __restrict__ noise,
                     float* __restrict__ out)
{
    int q = blockIdx.x * 128 + threadIdx.x;   // float4 index, 0..65535
    const int PL4 = N_NODES * N_NODES / 4;
    float4 p0 = ((const float4*)P)[q];
    float4 p1 = ((const float4*)P)[q + PL4];
    float4 p2 = ((const float4*)P)[q + 2 * PL4];
    float4 p3 = ((const float4*)P)[q + 3 * PL4];
    float4 ns = ((const float4*)noise)[q];

    int idx0 = q * 4;
    int i = idx0 >> 9;
    int jbase = idx0 & (N_NODES - 1);

    float pv[4] = { 0.25f * (p0.x + p1.x + p2.x + p3.x),
                    0.25f * (p0.y + p1.y + p2.y + p3.y),
                    0.25f * (p0.z + p1.z + p2.z + p3.z),
                    0.25f * (p0.w + p1.w + p2.w + p3.w) };
    float nv[4] = { ns.x, ns.y, ns.z, ns.w };
    float4 o;
    float* op = (float*)&o;
#pragma unroll
    for (int e = 0; e < 4; e++) {
        float p = pv[e];
        if (i == jbase + e) p = 0.f;
        float lp = __logf(p + 1e-10f) - __logf(1.0f + (1e-10f - p));
        lp = fminf(fmaxf(lp, -10.f), 10.f);
        float lo = __logf(nv[e]) - __logf(1.0f - nv[e]);
        float z = (lp + lo) * 5.0f;     // / TEMPERATURE (0.2)
        op[e] = 1.f / (1.f + __expf(-z));
    }
    ((float4*)out)[q] = o;
}

// ---------------------------------------------------------------------------
extern "C" void kernel_launch(void* const* d_in, const int* in_sizes, int n_in,
                              void* d_out, int out_size)
{
    const float* x     = (const float*)d_in[0];
    const float* W1    = (const float*)d_in[1];
    const float* b1    = (const float*)d_in[2];
    const float* W2    = (const float*)d_in[3];
    const float* b2    = (const float*)d_in[4];
    const float* Wp    = (const float*)d_in[5];
    const float* bp    = (const float*)d_in[6];
    const float* Wb    = (const float*)d_in[7];
    const float* bb    = (const float*)d_in[8];
    const float* noise = (const float*)d_in[9];
    float* out = (float*)d_out;

    float *X1, *X2, *S1, *S2P, *P;
    cudaGetSymbolAddress((void**)&X1,  g_X1);
    cudaGetSymbolAddress((void**)&X2,  g_X2);
    cudaGetSymbolAddress((void**)&S1,  g_S1);
    cudaGetSymbolAddress((void**)&S2P, g_S2P);
    cudaGetSymbolAddress((void**)&P,   g_P);

    const size_t gemm_smem = (size_t)GEMM_SMEM_FLOATS * sizeof(float);  // 55296 B
    cudaFuncSetAttribute(stage1_mma, cudaFuncAttributeMaxDynamicSharedMemorySize,
                         (int)gemm_smem);
    cudaFuncSetAttribute(stage2_mma, cudaFuncAttributeMaxDynamicSharedMemorySize,
                         (int)gemm_smem);

    // Stage 1: [X1|X2] = leaky(x @ [W1;W2]^T + bias)
    stage1_mma<<<dim3(MROWS / 32, 4), 256, gemm_smem>>>(x, W1, W2, b1, b2, X1, X2);

    // Stage 2: S1 = X1@Wp_a^T, S2P = X2@Wp_b^T + bp
    stage2_mma<<<dim3(MROWS / 32, 2, 2), 256, gemm_smem>>>(X1, X2, Wp, bp, S1, S2P);

    // Stage 3: pairwise sigmoid planes (64x64 tiles, one b per block)
    size_t pw_smem = (size_t)PW_U64_TOTAL * sizeof(u64);   // 68,096 B
    cudaFuncSetAttribute(pairwise_kernel,
                         cudaFuncAttributeMaxDynamicSharedMemorySize, (int)pw_smem);
    dim3 g3(N_NODES / 64, N_NODES / 64, BBATCH);   // 8 x 8 x 4 = 256
    pairwise_kernel<<<g3, dim3(128), pw_smem>>>(S1, S2P, Wb, bb, P);

    // Stage 4: epilogue
    finalize_kernel<<<N_NODES * N_NODES / 4 / 128, 128>>>(P, noise, out);
}